// round 6
// baseline (speedup 1.0000x reference)
#include <cuda_runtime.h>
#include <cuda_bf16.h>
#include <math.h>
#include <stdint.h>

// Problem constants
#define T   512
#define H   2048
#define E   64
#define TOPK 8
#define I   768

// Scratch (device globals — no allocation allowed)
__device__ int   g_count[E];
__device__ int   g_tok[E * T];
__device__ float g_wt[E * T];
__device__ float g_act[(size_t)E * T * I];   // routed SwiGLU activations
__device__ float g_h1[T * I];                // shared-expert intermediate

// ---------------------------------------------------------------------------
// helpers
// ---------------------------------------------------------------------------
__device__ __forceinline__ void split_bf16(float v, __nv_bfloat16& h, __nv_bfloat16& l) {
    h = __float2bfloat16(v);
    l = __float2bfloat16(v - __bfloat162float(h));
}

__device__ __forceinline__ void mma_bf16(float* c, uint32_t a0, uint32_t a1,
                                         uint32_t a2, uint32_t a3,
                                         uint32_t b0, uint32_t b1) {
    asm volatile(
        "mma.sync.aligned.m16n8k16.row.col.f32.bf16.bf16.f32 "
        "{%0,%1,%2,%3}, {%4,%5,%6,%7}, {%8,%9}, {%0,%1,%2,%3};"
        : "+f"(c[0]), "+f"(c[1]), "+f"(c[2]), "+f"(c[3])
        : "r"(a0), "r"(a1), "r"(a2), "r"(a3), "r"(b0), "r"(b1));
}

#define SMEM_LD32(arr, r, c) (*(const uint32_t*)&(arr)[r][c])

// ---------------------------------------------------------------------------
// 0) zero per-expert counters
// ---------------------------------------------------------------------------
__global__ void init_kernel() {
    int i = threadIdx.x;
    if (i < E) g_count[i] = 0;
}

// ---------------------------------------------------------------------------
// 1) router
// ---------------------------------------------------------------------------
__global__ void router_kernel(const float* __restrict__ x,
                              const float* __restrict__ gate_w,
                              const float* __restrict__ gate_b) {
    const int t = blockIdx.x;
    const int warp = threadIdx.x >> 5;
    const int lane = threadIdx.x & 31;
    __shared__ float s_scores[E];

    const float* xr = x + (size_t)t * H;
    for (int e = warp; e < E; e += 8) {
        const float* gw = gate_w + (size_t)e * H;
        float sum = 0.f;
        for (int h = lane; h < H; h += 32)
            sum += xr[h] * gw[h];
        #pragma unroll
        for (int o = 16; o > 0; o >>= 1)
            sum += __shfl_xor_sync(0xFFFFFFFFu, sum, o);
        if (lane == 0)
            s_scores[e] = 1.f / (1.f + expf(-sum));
    }
    __syncthreads();

    if (warp == 0) {
        float b0 = s_scores[lane]      + gate_b[lane];
        float b1 = s_scores[lane + 32] + gate_b[lane + 32];
        int   idx[TOPK];
        float wts[TOPK];
        float wsum = 0.f;
        #pragma unroll
        for (int k = 0; k < TOPK; k++) {
            float m;
            int   mi;
            if (b1 > b0) { m = b1; mi = lane + 32; }
            else         { m = b0; mi = lane; }
            #pragma unroll
            for (int o = 16; o > 0; o >>= 1) {
                float om = __shfl_xor_sync(0xFFFFFFFFu, m, o);
                int   oi = __shfl_xor_sync(0xFFFFFFFFu, mi, o);
                if (om > m || (om == m && oi < mi)) { m = om; mi = oi; }
            }
            idx[k] = mi;
            float sc = s_scores[mi];
            wts[k] = sc;
            wsum += sc;
            if (lane == (mi & 31)) {
                if (mi < 32) b0 = -INFINITY; else b1 = -INFINITY;
            }
        }
        float inv = 1.f / (wsum + 1e-20f);
        if (lane < TOPK) {
            int e = idx[lane];
            float w = wts[lane] * inv;
            int pos = atomicAdd(&g_count[e], 1);
            g_tok[e * T + pos] = t;
            g_wt[e * T + pos]  = w;
        }
    }
}

// ---------------------------------------------------------------------------
// 2) routed up-projection (split-bf16 mma, 64x64 tile, KC=32)
//    act = silu(x @ w_gate[e]) * (x @ w_up[e]); grid (I/64, E), 256 thr
// ---------------------------------------------------------------------------
__global__ __launch_bounds__(256) void expert_up_kernel(
        const float* __restrict__ x,
        const float* __restrict__ w_gate,
        const float* __restrict__ w_up) {
    const int e  = blockIdx.y;
    const int i0 = blockIdx.x * 64;
    const int cnt = g_count[e];
    if (cnt == 0) return;

    const int tid  = threadIdx.x;
    const int lane = tid & 31;
    const int wid  = tid >> 5;
    const int mw   = wid & 3;      // 4 warps over M (16 rows each)
    const int nw   = wid >> 2;     // 2 warps over N (32 cols each)
    const int gq   = lane >> 2;    // group id 0..7
    const int qp   = (lane & 3) * 2;

    __shared__ __nv_bfloat16 A_hi[64][40], A_lo[64][40];
    __shared__ __nv_bfloat16 Bg_hi[64][40], Bg_lo[64][40];
    __shared__ __nv_bfloat16 Bu_hi[64][40], Bu_lo[64][40];
    __shared__ int s_tok[64];

    const float* wg = w_gate + (size_t)e * H * I;
    const float* wu = w_up   + (size_t)e * H * I;

    for (int m0 = 0; m0 < cnt; m0 += 64) {
        if (tid < 64) {
            int r = m0 + tid;
            s_tok[tid] = (r < cnt) ? g_tok[e * T + r] : g_tok[e * T];
        }
        __syncthreads();

        float cg[4][4] = {};
        float cu[4][4] = {};

        for (int k0 = 0; k0 < H; k0 += 32) {
            // load A (gathered token rows), convert fp32 -> hi/lo bf16
            #pragma unroll
            for (int i = 0; i < 8; i++) {
                int elem = tid + i * 256;          // 0..2047
                int r = elem >> 5, c = elem & 31;
                float v = x[(size_t)s_tok[r] * H + k0 + c];
                split_bf16(v, A_hi[r][c], A_lo[r][c]);
            }
            // load B tiles (32 k-rows x 64 n-cols), store transposed [n][k]
            #pragma unroll
            for (int i = 0; i < 8; i++) {
                int elem = tid + i * 256;
                int kk = elem >> 6, n = elem & 63;
                float vg = wg[(size_t)(k0 + kk) * I + i0 + n];
                float vu = wu[(size_t)(k0 + kk) * I + i0 + n];
                split_bf16(vg, Bg_hi[n][kk], Bg_lo[n][kk]);
                split_bf16(vu, Bu_hi[n][kk], Bu_lo[n][kk]);
            }
            __syncthreads();

            #pragma unroll
            for (int ks = 0; ks < 2; ks++) {
                const int kb = ks * 16 + qp;
                const int r0 = 16 * mw + gq;
                uint32_t ah0 = SMEM_LD32(A_hi, r0,     kb);
                uint32_t ah1 = SMEM_LD32(A_hi, r0 + 8, kb);
                uint32_t ah2 = SMEM_LD32(A_hi, r0,     kb + 8);
                uint32_t ah3 = SMEM_LD32(A_hi, r0 + 8, kb + 8);
                uint32_t al0 = SMEM_LD32(A_lo, r0,     kb);
                uint32_t al1 = SMEM_LD32(A_lo, r0 + 8, kb);
                uint32_t al2 = SMEM_LD32(A_lo, r0,     kb + 8);
                uint32_t al3 = SMEM_LD32(A_lo, r0 + 8, kb + 8);
                #pragma unroll
                for (int nt = 0; nt < 4; nt++) {
                    const int nb = 32 * nw + 8 * nt + gq;
                    uint32_t bh0 = SMEM_LD32(Bg_hi, nb, kb);
                    uint32_t bh1 = SMEM_LD32(Bg_hi, nb, kb + 8);
                    uint32_t bl0 = SMEM_LD32(Bg_lo, nb, kb);
                    uint32_t bl1 = SMEM_LD32(Bg_lo, nb, kb + 8);
                    mma_bf16(cg[nt], ah0, ah1, ah2, ah3, bh0, bh1);
                    mma_bf16(cg[nt], ah0, ah1, ah2, ah3, bl0, bl1);
                    mma_bf16(cg[nt], al0, al1, al2, al3, bh0, bh1);
                    uint32_t uh0 = SMEM_LD32(Bu_hi, nb, kb);
                    uint32_t uh1 = SMEM_LD32(Bu_hi, nb, kb + 8);
                    uint32_t ul0 = SMEM_LD32(Bu_lo, nb, kb);
                    uint32_t ul1 = SMEM_LD32(Bu_lo, nb, kb + 8);
                    mma_bf16(cu[nt], ah0, ah1, ah2, ah3, uh0, uh1);
                    mma_bf16(cu[nt], ah0, ah1, ah2, ah3, ul0, ul1);
                    mma_bf16(cu[nt], al0, al1, al2, al3, uh0, uh1);
                }
            }
            __syncthreads();
        }

        // epilogue: silu(gate) * up -> g_act
        #pragma unroll
        for (int nt = 0; nt < 4; nt++) {
            const int col = i0 + 32 * nw + 8 * nt + qp;
            #pragma unroll
            for (int half = 0; half < 2; half++) {
                int r = m0 + 16 * mw + gq + half * 8;
                if (r < cnt) {
                    float gv0 = cg[nt][half * 2 + 0];
                    float gv1 = cg[nt][half * 2 + 1];
                    float s0 = gv0 / (1.f + __expf(-gv0));
                    float s1 = gv1 / (1.f + __expf(-gv1));
                    float2 o;
                    o.x = s0 * cu[nt][half * 2 + 0];
                    o.y = s1 * cu[nt][half * 2 + 1];
                    *(float2*)&g_act[((size_t)e * T + r) * I + col] = o;
                }
            }
        }
        __syncthreads();
    }
}

// ---------------------------------------------------------------------------
// 3) routed down-projection + weighted combine (split-bf16 mma)
//    grid (H/64, E), 256 thr
// ---------------------------------------------------------------------------
__global__ __launch_bounds__(256) void expert_down_kernel(
        const float* __restrict__ w_down,
        float* __restrict__ out) {
    const int e  = blockIdx.y;
    const int h0 = blockIdx.x * 64;
    const int cnt = g_count[e];
    if (cnt == 0) return;

    const int tid  = threadIdx.x;
    const int lane = tid & 31;
    const int wid  = tid >> 5;
    const int mw   = wid & 3;
    const int nw   = wid >> 2;
    const int gq   = lane >> 2;
    const int qp   = (lane & 3) * 2;

    __shared__ __nv_bfloat16 A_hi[64][40], A_lo[64][40];
    __shared__ __nv_bfloat16 B_hi[64][40], B_lo[64][40];
    __shared__ int   s_tok[64];
    __shared__ float s_wt[64];

    const float* wd = w_down + (size_t)e * I * H;

    for (int m0 = 0; m0 < cnt; m0 += 64) {
        if (tid < 64) {
            int r = m0 + tid;
            int rc = (r < cnt) ? r : (cnt - 1);
            s_tok[tid] = g_tok[e * T + rc];
            s_wt[tid]  = g_wt[e * T + rc];
        }
        __syncthreads();

        float cc[4][4] = {};

        for (int k0 = 0; k0 < I; k0 += 32) {
            #pragma unroll
            for (int i = 0; i < 8; i++) {
                int elem = tid + i * 256;
                int r = elem >> 5, c = elem & 31;
                int rr = m0 + r;
                if (rr >= cnt) rr = cnt - 1;
                float v = g_act[((size_t)e * T + rr) * I + k0 + c];
                split_bf16(v, A_hi[r][c], A_lo[r][c]);
            }
            #pragma unroll
            for (int i = 0; i < 8; i++) {
                int elem = tid + i * 256;
                int kk = elem >> 6, n = elem & 63;
                float v = wd[(size_t)(k0 + kk) * H + h0 + n];
                split_bf16(v, B_hi[n][kk], B_lo[n][kk]);
            }
            __syncthreads();

            #pragma unroll
            for (int ks = 0; ks < 2; ks++) {
                const int kb = ks * 16 + qp;
                const int r0 = 16 * mw + gq;
                uint32_t ah0 = SMEM_LD32(A_hi, r0,     kb);
                uint32_t ah1 = SMEM_LD32(A_hi, r0 + 8, kb);
                uint32_t ah2 = SMEM_LD32(A_hi, r0,     kb + 8);
                uint32_t ah3 = SMEM_LD32(A_hi, r0 + 8, kb + 8);
                uint32_t al0 = SMEM_LD32(A_lo, r0,     kb);
                uint32_t al1 = SMEM_LD32(A_lo, r0 + 8, kb);
                uint32_t al2 = SMEM_LD32(A_lo, r0,     kb + 8);
                uint32_t al3 = SMEM_LD32(A_lo, r0 + 8, kb + 8);
                #pragma unroll
                for (int nt = 0; nt < 4; nt++) {
                    const int nb = 32 * nw + 8 * nt + gq;
                    uint32_t bh0 = SMEM_LD32(B_hi, nb, kb);
                    uint32_t bh1 = SMEM_LD32(B_hi, nb, kb + 8);
                    uint32_t bl0 = SMEM_LD32(B_lo, nb, kb);
                    uint32_t bl1 = SMEM_LD32(B_lo, nb, kb + 8);
                    mma_bf16(cc[nt], ah0, ah1, ah2, ah3, bh0, bh1);
                    mma_bf16(cc[nt], ah0, ah1, ah2, ah3, bl0, bl1);
                    mma_bf16(cc[nt], al0, al1, al2, al3, bh0, bh1);
                }
            }
            __syncthreads();
        }

        #pragma unroll
        for (int nt = 0; nt < 4; nt++) {
            const int col = h0 + 32 * nw + 8 * nt + qp;
            #pragma unroll
            for (int half = 0; half < 2; half++) {
                int rl = 16 * mw + gq + half * 8;
                int r  = m0 + rl;
                if (r < cnt) {
                    int   tok = s_tok[rl];
                    float w   = s_wt[rl];
                    float* op = out + (size_t)tok * H + col;
                    atomicAdd(&op[0], w * cc[nt][half * 2 + 0]);
                    atomicAdd(&op[1], w * cc[nt][half * 2 + 1]);
                }
            }
        }
        __syncthreads();
    }
}

// ---------------------------------------------------------------------------
// 4a) shared expert up: h1 = silu(x @ sw_gate) * (x @ sw_up)
//     grid (I/64, T/64), 256 thr
// ---------------------------------------------------------------------------
__global__ __launch_bounds__(256) void shared_up_kernel(
        const float* __restrict__ x,
        const float* __restrict__ sw_gate,
        const float* __restrict__ sw_up) {
    const int m0 = blockIdx.y * 64;
    const int i0 = blockIdx.x * 64;
    const int tid  = threadIdx.x;
    const int lane = tid & 31;
    const int wid  = tid >> 5;
    const int mw   = wid & 3;
    const int nw   = wid >> 2;
    const int gq   = lane >> 2;
    const int qp   = (lane & 3) * 2;

    __shared__ __nv_bfloat16 A_hi[64][40], A_lo[64][40];
    __shared__ __nv_bfloat16 Bg_hi[64][40], Bg_lo[64][40];
    __shared__ __nv_bfloat16 Bu_hi[64][40], Bu_lo[64][40];

    float cg[4][4] = {};
    float cu[4][4] = {};

    for (int k0 = 0; k0 < H; k0 += 32) {
        #pragma unroll
        for (int i = 0; i < 8; i++) {
            int elem = tid + i * 256;
            int r = elem >> 5, c = elem & 31;
            float v = x[(size_t)(m0 + r) * H + k0 + c];
            split_bf16(v, A_hi[r][c], A_lo[r][c]);
        }
        #pragma unroll
        for (int i = 0; i < 8; i++) {
            int elem = tid + i * 256;
            int kk = elem >> 6, n = elem & 63;
            float vg = sw_gate[(size_t)(k0 + kk) * I + i0 + n];
            float vu = sw_up[(size_t)(k0 + kk) * I + i0 + n];
            split_bf16(vg, Bg_hi[n][kk], Bg_lo[n][kk]);
            split_bf16(vu, Bu_hi[n][kk], Bu_lo[n][kk]);
        }
        __syncthreads();

        #pragma unroll
        for (int ks = 0; ks < 2; ks++) {
            const int kb = ks * 16 + qp;
            const int r0 = 16 * mw + gq;
            uint32_t ah0 = SMEM_LD32(A_hi, r0,     kb);
            uint32_t ah1 = SMEM_LD32(A_hi, r0 + 8, kb);
            uint32_t ah2 = SMEM_LD32(A_hi, r0,     kb + 8);
            uint32_t ah3 = SMEM_LD32(A_hi, r0 + 8, kb + 8);
            uint32_t al0 = SMEM_LD32(A_lo, r0,     kb);
            uint32_t al1 = SMEM_LD32(A_lo, r0 + 8, kb);
            uint32_t al2 = SMEM_LD32(A_lo, r0,     kb + 8);
            uint32_t al3 = SMEM_LD32(A_lo, r0 + 8, kb + 8);
            #pragma unroll
            for (int nt = 0; nt < 4; nt++) {
                const int nb = 32 * nw + 8 * nt + gq;
                uint32_t bh0 = SMEM_LD32(Bg_hi, nb, kb);
                uint32_t bh1 = SMEM_LD32(Bg_hi, nb, kb + 8);
                uint32_t bl0 = SMEM_LD32(Bg_lo, nb, kb);
                uint32_t bl1 = SMEM_LD32(Bg_lo, nb, kb + 8);
                mma_bf16(cg[nt], ah0, ah1, ah2, ah3, bh0, bh1);
                mma_bf16(cg[nt], ah0, ah1, ah2, ah3, bl0, bl1);
                mma_bf16(cg[nt], al0, al1, al2, al3, bh0, bh1);
                uint32_t uh0 = SMEM_LD32(Bu_hi, nb, kb);
                uint32_t uh1 = SMEM_LD32(Bu_hi, nb, kb + 8);
                uint32_t ul0 = SMEM_LD32(Bu_lo, nb, kb);
                uint32_t ul1 = SMEM_LD32(Bu_lo, nb, kb + 8);
                mma_bf16(cu[nt], ah0, ah1, ah2, ah3, uh0, uh1);
                mma_bf16(cu[nt], ah0, ah1, ah2, ah3, ul0, ul1);
                mma_bf16(cu[nt], al0, al1, al2, al3, uh0, uh1);
            }
        }
        __syncthreads();
    }

    #pragma unroll
    for (int nt = 0; nt < 4; nt++) {
        const int col = i0 + 32 * nw + 8 * nt + qp;
        #pragma unroll
        for (int half = 0; half < 2; half++) {
            int r = m0 + 16 * mw + gq + half * 8;
            float gv0 = cg[nt][half * 2 + 0];
            float gv1 = cg[nt][half * 2 + 1];
            float s0 = gv0 / (1.f + __expf(-gv0));
            float s1 = gv1 / (1.f + __expf(-gv1));
            float2 o;
            o.x = s0 * cu[nt][half * 2 + 0];
            o.y = s1 * cu[nt][half * 2 + 1];
            *(float2*)&g_h1[(size_t)r * I + col] = o;
        }
    }
}

// ---------------------------------------------------------------------------
// 4b) shared expert down: out = h1 @ sw_down (plain store — initializes out)
//     grid (H/64, T/64), 256 thr
// ---------------------------------------------------------------------------
__global__ __launch_bounds__(256) void shared_down_kernel(
        const float* __restrict__ sw_down,
        float* __restrict__ out) {
    const int m0 = blockIdx.y * 64;
    const int h0 = blockIdx.x * 64;
    const int tid  = threadIdx.x;
    const int lane = tid & 31;
    const int wid  = tid >> 5;
    const int mw   = wid & 3;
    const int nw   = wid >> 2;
    const int gq   = lane >> 2;
    const int qp   = (lane & 3) * 2;

    __shared__ __nv_bfloat16 A_hi[64][40], A_lo[64][40];
    __shared__ __nv_bfloat16 B_hi[64][40], B_lo[64][40];

    float cc[4][4] = {};

    for (int k0 = 0; k0 < I; k0 += 32) {
        #pragma unroll
        for (int i = 0; i < 8; i++) {
            int elem = tid + i * 256;
            int r = elem >> 5, c = elem & 31;
            float v = g_h1[(size_t)(m0 + r) * I + k0 + c];
            split_bf16(v, A_hi[r][c], A_lo[r][c]);
        }
        #pragma unroll
        for (int i = 0; i < 8; i++) {
            int elem = tid + i * 256;
            int kk = elem >> 6, n = elem & 63;
            float v = sw_down[(size_t)(k0 + kk) * H + h0 + n];
            split_bf16(v, B_hi[n][kk], B_lo[n][kk]);
        }
        __syncthreads();

        #pragma unroll
        for (int ks = 0; ks < 2; ks++) {
            const int kb = ks * 16 + qp;
            const int r0 = 16 * mw + gq;
            uint32_t ah0 = SMEM_LD32(A_hi, r0,     kb);
            uint32_t ah1 = SMEM_LD32(A_hi, r0 + 8, kb);
            uint32_t ah2 = SMEM_LD32(A_hi, r0,     kb + 8);
            uint32_t ah3 = SMEM_LD32(A_hi, r0 + 8, kb + 8);
            uint32_t al0 = SMEM_LD32(A_lo, r0,     kb);
            uint32_t al1 = SMEM_LD32(A_lo, r0 + 8, kb);
            uint32_t al2 = SMEM_LD32(A_lo, r0,     kb + 8);
            uint32_t al3 = SMEM_LD32(A_lo, r0 + 8, kb + 8);
            #pragma unroll
            for (int nt = 0; nt < 4; nt++) {
                const int nb = 32 * nw + 8 * nt + gq;
                uint32_t bh0 = SMEM_LD32(B_hi, nb, kb);
                uint32_t bh1 = SMEM_LD32(B_hi, nb, kb + 8);
                uint32_t bl0 = SMEM_LD32(B_lo, nb, kb);
                uint32_t bl1 = SMEM_LD32(B_lo, nb, kb + 8);
                mma_bf16(cc[nt], ah0, ah1, ah2, ah3, bh0, bh1);
                mma_bf16(cc[nt], ah0, ah1, ah2, ah3, bl0, bl1);
                mma_bf16(cc[nt], al0, al1, al2, al3, bh0, bh1);
            }
        }
        __syncthreads();
    }

    #pragma unroll
    for (int nt = 0; nt < 4; nt++) {
        const int col = h0 + 32 * nw + 8 * nt + qp;
        #pragma unroll
        for (int half = 0; half < 2; half++) {
            int r = m0 + 16 * mw + gq + half * 8;
            float2 o;
            o.x = cc[nt][half * 2 + 0];
            o.y = cc[nt][half * 2 + 1];
            *(float2*)&out[(size_t)r * H + col] = o;
        }
    }
}

// ---------------------------------------------------------------------------
// launch
// ---------------------------------------------------------------------------
extern "C" void kernel_launch(void* const* d_in, const int* in_sizes, int n_in,
                              void* d_out, int out_size) {
    const float* x       = (const float*)d_in[0];
    const float* gate_w  = (const float*)d_in[1];
    const float* gate_b  = (const float*)d_in[2];
    const float* w_gate  = (const float*)d_in[3];
    const float* w_up    = (const float*)d_in[4];
    const float* w_down  = (const float*)d_in[5];
    const float* sw_gate = (const float*)d_in[6];
    const float* sw_up   = (const float*)d_in[7];
    const float* sw_down = (const float*)d_in[8];
    float* out = (float*)d_out;

    init_kernel<<<1, 64>>>();
    router_kernel<<<T, 256>>>(x, gate_w, gate_b);
    shared_up_kernel<<<dim3(I / 64, T / 64), 256>>>(x, sw_gate, sw_up);
    shared_down_kernel<<<dim3(H / 64, T / 64), 256>>>(sw_down, out);
    expert_up_kernel<<<dim3(I / 64, E), 256>>>(x, w_gate, w_up);
    expert_down_kernel<<<dim3(H / 64, E), 256>>>(w_down, out);
}

// round 17
// speedup vs baseline: 1.4178x; 1.4178x over previous
#include <cuda_runtime.h>
#include <cuda_bf16.h>
#include <math.h>
#include <stdint.h>

// Problem constants
#define T   512
#define H   2048
#define E   64
#define TOPK 8
#define I   768

// Scratch (device globals — no allocation allowed)
__device__ int   g_count[E];
__device__ int   g_tok[E * T];
__device__ float g_wt[E * T];
__device__ float g_act[(size_t)E * T * I];   // routed SwiGLU activations
__device__ float g_h1[T * I];                // shared-expert intermediate

// ---------------------------------------------------------------------------
// helpers
// ---------------------------------------------------------------------------
__device__ __forceinline__ void split_bf16(float v, __nv_bfloat16& h, __nv_bfloat16& l) {
    h = __float2bfloat16(v);
    l = __float2bfloat16(v - __bfloat162float(h));
}

// split a float4 into 4 contiguous hi / lo bf16 slots
__device__ __forceinline__ void split4_row(float4 v, __nv_bfloat16* h, __nv_bfloat16* l) {
    split_bf16(v.x, h[0], l[0]);
    split_bf16(v.y, h[1], l[1]);
    split_bf16(v.z, h[2], l[2]);
    split_bf16(v.w, h[3], l[3]);
}

__device__ __forceinline__ void mma_bf16(float* c, uint32_t a0, uint32_t a1,
                                         uint32_t a2, uint32_t a3,
                                         uint32_t b0, uint32_t b1) {
    asm volatile(
        "mma.sync.aligned.m16n8k16.row.col.f32.bf16.bf16.f32 "
        "{%0,%1,%2,%3}, {%4,%5,%6,%7}, {%8,%9}, {%0,%1,%2,%3};"
        : "+f"(c[0]), "+f"(c[1]), "+f"(c[2]), "+f"(c[3])
        : "r"(a0), "r"(a1), "r"(a2), "r"(a3), "r"(b0), "r"(b1));
}

#define SMEM_LD32(arr, r, c) (*(const uint32_t*)&(arr)[r][c])

// ---------------------------------------------------------------------------
// 0) zero per-expert counters
// ---------------------------------------------------------------------------
__global__ void init_kernel() {
    int i = threadIdx.x;
    if (i < E) g_count[i] = 0;
}

// ---------------------------------------------------------------------------
// 1) router
// ---------------------------------------------------------------------------
__global__ void router_kernel(const float* __restrict__ x,
                              const float* __restrict__ gate_w,
                              const float* __restrict__ gate_b) {
    const int t = blockIdx.x;
    const int warp = threadIdx.x >> 5;
    const int lane = threadIdx.x & 31;
    __shared__ float s_scores[E];

    const float* xr = x + (size_t)t * H;
    for (int e = warp; e < E; e += 8) {
        const float* gw = gate_w + (size_t)e * H;
        float sum = 0.f;
        for (int h = lane; h < H; h += 32)
            sum += xr[h] * gw[h];
        #pragma unroll
        for (int o = 16; o > 0; o >>= 1)
            sum += __shfl_xor_sync(0xFFFFFFFFu, sum, o);
        if (lane == 0)
            s_scores[e] = 1.f / (1.f + expf(-sum));
    }
    __syncthreads();

    if (warp == 0) {
        float b0 = s_scores[lane]      + gate_b[lane];
        float b1 = s_scores[lane + 32] + gate_b[lane + 32];
        int   idx[TOPK];
        float wts[TOPK];
        float wsum = 0.f;
        #pragma unroll
        for (int k = 0; k < TOPK; k++) {
            float m;
            int   mi;
            if (b1 > b0) { m = b1; mi = lane + 32; }
            else         { m = b0; mi = lane; }
            #pragma unroll
            for (int o = 16; o > 0; o >>= 1) {
                float om = __shfl_xor_sync(0xFFFFFFFFu, m, o);
                int   oi = __shfl_xor_sync(0xFFFFFFFFu, mi, o);
                if (om > m || (om == m && oi < mi)) { m = om; mi = oi; }
            }
            idx[k] = mi;
            float sc = s_scores[mi];
            wts[k] = sc;
            wsum += sc;
            if (lane == (mi & 31)) {
                if (mi < 32) b0 = -INFINITY; else b1 = -INFINITY;
            }
        }
        float inv = 1.f / (wsum + 1e-20f);
        if (lane < TOPK) {
            int e = idx[lane];
            float w = wts[lane] * inv;
            int pos = atomicAdd(&g_count[e], 1);
            g_tok[e * T + pos] = t;
            g_wt[e * T + pos]  = w;
        }
    }
}

// ---------------------------------------------------------------------------
// 2) routed up-projection: pipelined split-bf16 mma, 64x64 tile, KC=32
//    grid (I/64, E), 256 thr
// ---------------------------------------------------------------------------
__global__ __launch_bounds__(256, 2) void expert_up_kernel(
        const float* __restrict__ x,
        const float* __restrict__ w_gate,
        const float* __restrict__ w_up) {
    const int e  = blockIdx.y;
    const int i0 = blockIdx.x * 64;
    const int cnt = g_count[e];
    if (cnt == 0) return;

    const int tid  = threadIdx.x;
    const int lane = tid & 31;
    const int wid  = tid >> 5;
    const int mw   = wid & 3;
    const int nw   = wid >> 2;
    const int gq   = lane >> 2;
    const int qp   = (lane & 3) * 2;

    // vector-load index map
    const int a_r  = tid >> 3;            // 0..31 (i=0), +32 for i=1
    const int a_c  = (tid & 7) * 4;       // 0..28
    const int b_k  = tid >> 4;            // 0..15 (i=0), +16 for i=1
    const int b_n  = (tid & 15) * 4;      // 0..60

    __shared__ __nv_bfloat16 A_hi[64][40], A_lo[64][40];
    __shared__ __nv_bfloat16 Bg_hi[64][40], Bg_lo[64][40];
    __shared__ __nv_bfloat16 Bu_hi[64][40], Bu_lo[64][40];
    __shared__ int s_tok[64];

    const float* wg = w_gate + (size_t)e * H * I;
    const float* wu = w_up   + (size_t)e * H * I;

    for (int m0 = 0; m0 < cnt; m0 += 64) {
        if (tid < 64) {
            int r = m0 + tid;
            s_tok[tid] = (r < cnt) ? g_tok[e * T + r] : g_tok[e * T];
        }
        __syncthreads();

        const size_t tok0 = (size_t)s_tok[a_r] * H;
        const size_t tok1 = (size_t)s_tok[a_r + 32] * H;

        float cg[4][4] = {};
        float cu[4][4] = {};

        float4 rA0, rA1, rG0, rG1, rU0, rU1;

        // prologue: fill chunk 0
        {
            rA0 = *(const float4*)&x[tok0 + a_c];
            rA1 = *(const float4*)&x[tok1 + a_c];
            rG0 = *(const float4*)&wg[(size_t)b_k * I + i0 + b_n];
            rG1 = *(const float4*)&wg[(size_t)(b_k + 16) * I + i0 + b_n];
            rU0 = *(const float4*)&wu[(size_t)b_k * I + i0 + b_n];
            rU1 = *(const float4*)&wu[(size_t)(b_k + 16) * I + i0 + b_n];
            split4_row(rA0, &A_hi[a_r][a_c], &A_lo[a_r][a_c]);
            split4_row(rA1, &A_hi[a_r + 32][a_c], &A_lo[a_r + 32][a_c]);
            #pragma unroll
            for (int j = 0; j < 4; j++) {
                float gv = (&rG0.x)[j], g2 = (&rG1.x)[j];
                float uv = (&rU0.x)[j], u2 = (&rU1.x)[j];
                split_bf16(gv, Bg_hi[b_n + j][b_k],      Bg_lo[b_n + j][b_k]);
                split_bf16(g2, Bg_hi[b_n + j][b_k + 16], Bg_lo[b_n + j][b_k + 16]);
                split_bf16(uv, Bu_hi[b_n + j][b_k],      Bu_lo[b_n + j][b_k]);
                split_bf16(u2, Bu_hi[b_n + j][b_k + 16], Bu_lo[b_n + j][b_k + 16]);
            }
        }
        __syncthreads();

        const int nch = H / 32;
        for (int ch = 0; ch < nch; ch++) {
            // prefetch next chunk into registers (overlaps with mma below)
            if (ch + 1 < nch) {
                const int k0 = (ch + 1) * 32;
                rA0 = *(const float4*)&x[tok0 + k0 + a_c];
                rA1 = *(const float4*)&x[tok1 + k0 + a_c];
                rG0 = *(const float4*)&wg[(size_t)(k0 + b_k) * I + i0 + b_n];
                rG1 = *(const float4*)&wg[(size_t)(k0 + b_k + 16) * I + i0 + b_n];
                rU0 = *(const float4*)&wu[(size_t)(k0 + b_k) * I + i0 + b_n];
                rU1 = *(const float4*)&wu[(size_t)(k0 + b_k + 16) * I + i0 + b_n];
            }

            #pragma unroll
            for (int ks = 0; ks < 2; ks++) {
                const int kb = ks * 16 + qp;
                const int r0 = 16 * mw + gq;
                uint32_t ah0 = SMEM_LD32(A_hi, r0,     kb);
                uint32_t ah1 = SMEM_LD32(A_hi, r0 + 8, kb);
                uint32_t ah2 = SMEM_LD32(A_hi, r0,     kb + 8);
                uint32_t ah3 = SMEM_LD32(A_hi, r0 + 8, kb + 8);
                uint32_t al0 = SMEM_LD32(A_lo, r0,     kb);
                uint32_t al1 = SMEM_LD32(A_lo, r0 + 8, kb);
                uint32_t al2 = SMEM_LD32(A_lo, r0,     kb + 8);
                uint32_t al3 = SMEM_LD32(A_lo, r0 + 8, kb + 8);
                #pragma unroll
                for (int nt = 0; nt < 4; nt++) {
                    const int nb = 32 * nw + 8 * nt + gq;
                    uint32_t bh0 = SMEM_LD32(Bg_hi, nb, kb);
                    uint32_t bh1 = SMEM_LD32(Bg_hi, nb, kb + 8);
                    uint32_t bl0 = SMEM_LD32(Bg_lo, nb, kb);
                    uint32_t bl1 = SMEM_LD32(Bg_lo, nb, kb + 8);
                    mma_bf16(cg[nt], ah0, ah1, ah2, ah3, bh0, bh1);
                    mma_bf16(cg[nt], ah0, ah1, ah2, ah3, bl0, bl1);
                    mma_bf16(cg[nt], al0, al1, al2, al3, bh0, bh1);
                    uint32_t uh0 = SMEM_LD32(Bu_hi, nb, kb);
                    uint32_t uh1 = SMEM_LD32(Bu_hi, nb, kb + 8);
                    uint32_t ul0 = SMEM_LD32(Bu_lo, nb, kb);
                    uint32_t ul1 = SMEM_LD32(Bu_lo, nb, kb + 8);
                    mma_bf16(cu[nt], ah0, ah1, ah2, ah3, uh0, uh1);
                    mma_bf16(cu[nt], ah0, ah1, ah2, ah3, ul0, ul1);
                    mma_bf16(cu[nt], al0, al1, al2, al3, uh0, uh1);
                }
            }
            __syncthreads();

            if (ch + 1 < nch) {
                split4_row(rA0, &A_hi[a_r][a_c], &A_lo[a_r][a_c]);
                split4_row(rA1, &A_hi[a_r + 32][a_c], &A_lo[a_r + 32][a_c]);
                #pragma unroll
                for (int j = 0; j < 4; j++) {
                    float gv = (&rG0.x)[j], g2 = (&rG1.x)[j];
                    float uv = (&rU0.x)[j], u2 = (&rU1.x)[j];
                    split_bf16(gv, Bg_hi[b_n + j][b_k],      Bg_lo[b_n + j][b_k]);
                    split_bf16(g2, Bg_hi[b_n + j][b_k + 16], Bg_lo[b_n + j][b_k + 16]);
                    split_bf16(uv, Bu_hi[b_n + j][b_k],      Bu_lo[b_n + j][b_k]);
                    split_bf16(u2, Bu_hi[b_n + j][b_k + 16], Bu_lo[b_n + j][b_k + 16]);
                }
                __syncthreads();
            }
        }

        // epilogue: silu(gate) * up -> g_act
        #pragma unroll
        for (int nt = 0; nt < 4; nt++) {
            const int col = i0 + 32 * nw + 8 * nt + qp;
            #pragma unroll
            for (int half = 0; half < 2; half++) {
                int r = m0 + 16 * mw + gq + half * 8;
                if (r < cnt) {
                    float gv0 = cg[nt][half * 2 + 0];
                    float gv1 = cg[nt][half * 2 + 1];
                    float s0 = gv0 / (1.f + __expf(-gv0));
                    float s1 = gv1 / (1.f + __expf(-gv1));
                    float2 o;
                    o.x = s0 * cu[nt][half * 2 + 0];
                    o.y = s1 * cu[nt][half * 2 + 1];
                    *(float2*)&g_act[((size_t)e * T + r) * I + col] = o;
                }
            }
        }
        __syncthreads();
    }
}

// ---------------------------------------------------------------------------
// 3) routed down-projection + weighted combine (pipelined)
//    grid (H/64, E), 256 thr
// ---------------------------------------------------------------------------
__global__ __launch_bounds__(256, 2) void expert_down_kernel(
        const float* __restrict__ w_down,
        float* __restrict__ out) {
    const int e  = blockIdx.y;
    const int h0 = blockIdx.x * 64;
    const int cnt = g_count[e];
    if (cnt == 0) return;

    const int tid  = threadIdx.x;
    const int lane = tid & 31;
    const int wid  = tid >> 5;
    const int mw   = wid & 3;
    const int nw   = wid >> 2;
    const int gq   = lane >> 2;
    const int qp   = (lane & 3) * 2;

    const int a_r  = tid >> 3;
    const int a_c  = (tid & 7) * 4;
    const int b_k  = tid >> 4;
    const int b_n  = (tid & 15) * 4;

    __shared__ __nv_bfloat16 A_hi[64][40], A_lo[64][40];
    __shared__ __nv_bfloat16 B_hi[64][40], B_lo[64][40];
    __shared__ int   s_tok[64];
    __shared__ float s_wt[64];

    const float* wd = w_down + (size_t)e * I * H;

    for (int m0 = 0; m0 < cnt; m0 += 64) {
        if (tid < 64) {
            int r = m0 + tid;
            int rc = (r < cnt) ? r : (cnt - 1);
            s_tok[tid] = g_tok[e * T + rc];
            s_wt[tid]  = g_wt[e * T + rc];
        }
        __syncthreads();

        int rr0 = m0 + a_r;        if (rr0 >= cnt) rr0 = cnt - 1;
        int rr1 = m0 + a_r + 32;   if (rr1 >= cnt) rr1 = cnt - 1;
        const size_t ab0 = ((size_t)e * T + rr0) * I;
        const size_t ab1 = ((size_t)e * T + rr1) * I;

        float cc[4][4] = {};
        float4 rA0, rA1, rB0, rB1;

        {
            rA0 = *(const float4*)&g_act[ab0 + a_c];
            rA1 = *(const float4*)&g_act[ab1 + a_c];
            rB0 = *(const float4*)&wd[(size_t)b_k * H + h0 + b_n];
            rB1 = *(const float4*)&wd[(size_t)(b_k + 16) * H + h0 + b_n];
            split4_row(rA0, &A_hi[a_r][a_c], &A_lo[a_r][a_c]);
            split4_row(rA1, &A_hi[a_r + 32][a_c], &A_lo[a_r + 32][a_c]);
            #pragma unroll
            for (int j = 0; j < 4; j++) {
                split_bf16((&rB0.x)[j], B_hi[b_n + j][b_k],      B_lo[b_n + j][b_k]);
                split_bf16((&rB1.x)[j], B_hi[b_n + j][b_k + 16], B_lo[b_n + j][b_k + 16]);
            }
        }
        __syncthreads();

        const int nch = I / 32;
        for (int ch = 0; ch < nch; ch++) {
            if (ch + 1 < nch) {
                const int k0 = (ch + 1) * 32;
                rA0 = *(const float4*)&g_act[ab0 + k0 + a_c];
                rA1 = *(const float4*)&g_act[ab1 + k0 + a_c];
                rB0 = *(const float4*)&wd[(size_t)(k0 + b_k) * H + h0 + b_n];
                rB1 = *(const float4*)&wd[(size_t)(k0 + b_k + 16) * H + h0 + b_n];
            }

            #pragma unroll
            for (int ks = 0; ks < 2; ks++) {
                const int kb = ks * 16 + qp;
                const int r0 = 16 * mw + gq;
                uint32_t ah0 = SMEM_LD32(A_hi, r0,     kb);
                uint32_t ah1 = SMEM_LD32(A_hi, r0 + 8, kb);
                uint32_t ah2 = SMEM_LD32(A_hi, r0,     kb + 8);
                uint32_t ah3 = SMEM_LD32(A_hi, r0 + 8, kb + 8);
                uint32_t al0 = SMEM_LD32(A_lo, r0,     kb);
                uint32_t al1 = SMEM_LD32(A_lo, r0 + 8, kb);
                uint32_t al2 = SMEM_LD32(A_lo, r0,     kb + 8);
                uint32_t al3 = SMEM_LD32(A_lo, r0 + 8, kb + 8);
                #pragma unroll
                for (int nt = 0; nt < 4; nt++) {
                    const int nb = 32 * nw + 8 * nt + gq;
                    uint32_t bh0 = SMEM_LD32(B_hi, nb, kb);
                    uint32_t bh1 = SMEM_LD32(B_hi, nb, kb + 8);
                    uint32_t bl0 = SMEM_LD32(B_lo, nb, kb);
                    uint32_t bl1 = SMEM_LD32(B_lo, nb, kb + 8);
                    mma_bf16(cc[nt], ah0, ah1, ah2, ah3, bh0, bh1);
                    mma_bf16(cc[nt], ah0, ah1, ah2, ah3, bl0, bl1);
                    mma_bf16(cc[nt], al0, al1, al2, al3, bh0, bh1);
                }
            }
            __syncthreads();

            if (ch + 1 < nch) {
                split4_row(rA0, &A_hi[a_r][a_c], &A_lo[a_r][a_c]);
                split4_row(rA1, &A_hi[a_r + 32][a_c], &A_lo[a_r + 32][a_c]);
                #pragma unroll
                for (int j = 0; j < 4; j++) {
                    split_bf16((&rB0.x)[j], B_hi[b_n + j][b_k],      B_lo[b_n + j][b_k]);
                    split_bf16((&rB1.x)[j], B_hi[b_n + j][b_k + 16], B_lo[b_n + j][b_k + 16]);
                }
                __syncthreads();
            }
        }

        #pragma unroll
        for (int nt = 0; nt < 4; nt++) {
            const int col = h0 + 32 * nw + 8 * nt + qp;
            #pragma unroll
            for (int half = 0; half < 2; half++) {
                int rl = 16 * mw + gq + half * 8;
                int r  = m0 + rl;
                if (r < cnt) {
                    int   tok = s_tok[rl];
                    float w   = s_wt[rl];
                    float* op = out + (size_t)tok * H + col;
                    atomicAdd(&op[0], w * cc[nt][half * 2 + 0]);
                    atomicAdd(&op[1], w * cc[nt][half * 2 + 1]);
                }
            }
        }
        __syncthreads();
    }
}

// ---------------------------------------------------------------------------
// 4a) shared expert up (pipelined): grid (I/64, T/64), 256 thr
// ---------------------------------------------------------------------------
__global__ __launch_bounds__(256, 2) void shared_up_kernel(
        const float* __restrict__ x,
        const float* __restrict__ sw_gate,
        const float* __restrict__ sw_up) {
    const int m0 = blockIdx.y * 64;
    const int i0 = blockIdx.x * 64;
    const int tid  = threadIdx.x;
    const int lane = tid & 31;
    const int wid  = tid >> 5;
    const int mw   = wid & 3;
    const int nw   = wid >> 2;
    const int gq   = lane >> 2;
    const int qp   = (lane & 3) * 2;

    const int a_r  = tid >> 3;
    const int a_c  = (tid & 7) * 4;
    const int b_k  = tid >> 4;
    const int b_n  = (tid & 15) * 4;

    __shared__ __nv_bfloat16 A_hi[64][40], A_lo[64][40];
    __shared__ __nv_bfloat16 Bg_hi[64][40], Bg_lo[64][40];
    __shared__ __nv_bfloat16 Bu_hi[64][40], Bu_lo[64][40];

    const size_t ab0 = (size_t)(m0 + a_r) * H;
    const size_t ab1 = (size_t)(m0 + a_r + 32) * H;

    float cg[4][4] = {};
    float cu[4][4] = {};
    float4 rA0, rA1, rG0, rG1, rU0, rU1;

    {
        rA0 = *(const float4*)&x[ab0 + a_c];
        rA1 = *(const float4*)&x[ab1 + a_c];
        rG0 = *(const float4*)&sw_gate[(size_t)b_k * I + i0 + b_n];
        rG1 = *(const float4*)&sw_gate[(size_t)(b_k + 16) * I + i0 + b_n];
        rU0 = *(const float4*)&sw_up[(size_t)b_k * I + i0 + b_n];
        rU1 = *(const float4*)&sw_up[(size_t)(b_k + 16) * I + i0 + b_n];
        split4_row(rA0, &A_hi[a_r][a_c], &A_lo[a_r][a_c]);
        split4_row(rA1, &A_hi[a_r + 32][a_c], &A_lo[a_r + 32][a_c]);
        #pragma unroll
        for (int j = 0; j < 4; j++) {
            split_bf16((&rG0.x)[j], Bg_hi[b_n + j][b_k],      Bg_lo[b_n + j][b_k]);
            split_bf16((&rG1.x)[j], Bg_hi[b_n + j][b_k + 16], Bg_lo[b_n + j][b_k + 16]);
            split_bf16((&rU0.x)[j], Bu_hi[b_n + j][b_k],      Bu_lo[b_n + j][b_k]);
            split_bf16((&rU1.x)[j], Bu_hi[b_n + j][b_k + 16], Bu_lo[b_n + j][b_k + 16]);
        }
    }
    __syncthreads();

    const int nch = H / 32;
    for (int ch = 0; ch < nch; ch++) {
        if (ch + 1 < nch) {
            const int k0 = (ch + 1) * 32;
            rA0 = *(const float4*)&x[ab0 + k0 + a_c];
            rA1 = *(const float4*)&x[ab1 + k0 + a_c];
            rG0 = *(const float4*)&sw_gate[(size_t)(k0 + b_k) * I + i0 + b_n];
            rG1 = *(const float4*)&sw_gate[(size_t)(k0 + b_k + 16) * I + i0 + b_n];
            rU0 = *(const float4*)&sw_up[(size_t)(k0 + b_k) * I + i0 + b_n];
            rU1 = *(const float4*)&sw_up[(size_t)(k0 + b_k + 16) * I + i0 + b_n];
        }

        #pragma unroll
        for (int ks = 0; ks < 2; ks++) {
            const int kb = ks * 16 + qp;
            const int r0 = 16 * mw + gq;
            uint32_t ah0 = SMEM_LD32(A_hi, r0,     kb);
            uint32_t ah1 = SMEM_LD32(A_hi, r0 + 8, kb);
            uint32_t ah2 = SMEM_LD32(A_hi, r0,     kb + 8);
            uint32_t ah3 = SMEM_LD32(A_hi, r0 + 8, kb + 8);
            uint32_t al0 = SMEM_LD32(A_lo, r0,     kb);
            uint32_t al1 = SMEM_LD32(A_lo, r0 + 8, kb);
            uint32_t al2 = SMEM_LD32(A_lo, r0,     kb + 8);
            uint32_t al3 = SMEM_LD32(A_lo, r0 + 8, kb + 8);
            #pragma unroll
            for (int nt = 0; nt < 4; nt++) {
                const int nb = 32 * nw + 8 * nt + gq;
                uint32_t bh0 = SMEM_LD32(Bg_hi, nb, kb);
                uint32_t bh1 = SMEM_LD32(Bg_hi, nb, kb + 8);
                uint32_t bl0 = SMEM_LD32(Bg_lo, nb, kb);
                uint32_t bl1 = SMEM_LD32(Bg_lo, nb, kb + 8);
                mma_bf16(cg[nt], ah0, ah1, ah2, ah3, bh0, bh1);
                mma_bf16(cg[nt], ah0, ah1, ah2, ah3, bl0, bl1);
                mma_bf16(cg[nt], al0, al1, al2, al3, bh0, bh1);
                uint32_t uh0 = SMEM_LD32(Bu_hi, nb, kb);
                uint32_t uh1 = SMEM_LD32(Bu_hi, nb, kb + 8);
                uint32_t ul0 = SMEM_LD32(Bu_lo, nb, kb);
                uint32_t ul1 = SMEM_LD32(Bu_lo, nb, kb + 8);
                mma_bf16(cu[nt], ah0, ah1, ah2, ah3, uh0, uh1);
                mma_bf16(cu[nt], ah0, ah1, ah2, ah3, ul0, ul1);
                mma_bf16(cu[nt], al0, al1, al2, al3, uh0, uh1);
            }
        }
        __syncthreads();

        if (ch + 1 < nch) {
            split4_row(rA0, &A_hi[a_r][a_c], &A_lo[a_r][a_c]);
            split4_row(rA1, &A_hi[a_r + 32][a_c], &A_lo[a_r + 32][a_c]);
            #pragma unroll
            for (int j = 0; j < 4; j++) {
                split_bf16((&rG0.x)[j], Bg_hi[b_n + j][b_k],      Bg_lo[b_n + j][b_k]);
                split_bf16((&rG1.x)[j], Bg_hi[b_n + j][b_k + 16], Bg_lo[b_n + j][b_k + 16]);
                split_bf16((&rU0.x)[j], Bu_hi[b_n + j][b_k],      Bu_lo[b_n + j][b_k]);
                split_bf16((&rU1.x)[j], Bu_hi[b_n + j][b_k + 16], Bu_lo[b_n + j][b_k + 16]);
            }
            __syncthreads();
        }
    }

    #pragma unroll
    for (int nt = 0; nt < 4; nt++) {
        const int col = i0 + 32 * nw + 8 * nt + qp;
        #pragma unroll
        for (int half = 0; half < 2; half++) {
            int r = m0 + 16 * mw + gq + half * 8;
            float gv0 = cg[nt][half * 2 + 0];
            float gv1 = cg[nt][half * 2 + 1];
            float s0 = gv0 / (1.f + __expf(-gv0));
            float s1 = gv1 / (1.f + __expf(-gv1));
            float2 o;
            o.x = s0 * cu[nt][half * 2 + 0];
            o.y = s1 * cu[nt][half * 2 + 1];
            *(float2*)&g_h1[(size_t)r * I + col] = o;
        }
    }
}

// ---------------------------------------------------------------------------
// 4b) shared expert down (pipelined): grid (H/64, T/64), 256 thr
// ---------------------------------------------------------------------------
__global__ __launch_bounds__(256, 2) void shared_down_kernel(
        const float* __restrict__ sw_down,
        float* __restrict__ out) {
    const int m0 = blockIdx.y * 64;
    const int h0 = blockIdx.x * 64;
    const int tid  = threadIdx.x;
    const int lane = tid & 31;
    const int wid  = tid >> 5;
    const int mw   = wid & 3;
    const int nw   = wid >> 2;
    const int gq   = lane >> 2;
    const int qp   = (lane & 3) * 2;

    const int a_r  = tid >> 3;
    const int a_c  = (tid & 7) * 4;
    const int b_k  = tid >> 4;
    const int b_n  = (tid & 15) * 4;

    __shared__ __nv_bfloat16 A_hi[64][40], A_lo[64][40];
    __shared__ __nv_bfloat16 B_hi[64][40], B_lo[64][40];

    const size_t ab0 = (size_t)(m0 + a_r) * I;
    const size_t ab1 = (size_t)(m0 + a_r + 32) * I;

    float cc[4][4] = {};
    float4 rA0, rA1, rB0, rB1;

    {
        rA0 = *(const float4*)&g_h1[ab0 + a_c];
        rA1 = *(const float4*)&g_h1[ab1 + a_c];
        rB0 = *(const float4*)&sw_down[(size_t)b_k * H + h0 + b_n];
        rB1 = *(const float4*)&sw_down[(size_t)(b_k + 16) * H + h0 + b_n];
        split4_row(rA0, &A_hi[a_r][a_c], &A_lo[a_r][a_c]);
        split4_row(rA1, &A_hi[a_r + 32][a_c], &A_lo[a_r + 32][a_c]);
        #pragma unroll
        for (int j = 0; j < 4; j++) {
            split_bf16((&rB0.x)[j], B_hi[b_n + j][b_k],      B_lo[b_n + j][b_k]);
            split_bf16((&rB1.x)[j], B_hi[b_n + j][b_k + 16], B_lo[b_n + j][b_k + 16]);
        }
    }
    __syncthreads();

    const int nch = I / 32;
    for (int ch = 0; ch < nch; ch++) {
        if (ch + 1 < nch) {
            const int k0 = (ch + 1) * 32;
            rA0 = *(const float4*)&g_h1[ab0 + k0 + a_c];
            rA1 = *(const float4*)&g_h1[ab1 + k0 + a_c];
            rB0 = *(const float4*)&sw_down[(size_t)(k0 + b_k) * H + h0 + b_n];
            rB1 = *(const float4*)&sw_down[(size_t)(k0 + b_k + 16) * H + h0 + b_n];
        }

        #pragma unroll
        for (int ks = 0; ks < 2; ks++) {
            const int kb = ks * 16 + qp;
            const int r0 = 16 * mw + gq;
            uint32_t ah0 = SMEM_LD32(A_hi, r0,     kb);
            uint32_t ah1 = SMEM_LD32(A_hi, r0 + 8, kb);
            uint32_t ah2 = SMEM_LD32(A_hi, r0,     kb + 8);
            uint32_t ah3 = SMEM_LD32(A_hi, r0 + 8, kb + 8);
            uint32_t al0 = SMEM_LD32(A_lo, r0,     kb);
            uint32_t al1 = SMEM_LD32(A_lo, r0 + 8, kb);
            uint32_t al2 = SMEM_LD32(A_lo, r0,     kb + 8);
            uint32_t al3 = SMEM_LD32(A_lo, r0 + 8, kb + 8);
            #pragma unroll
            for (int nt = 0; nt < 4; nt++) {
                const int nb = 32 * nw + 8 * nt + gq;
                uint32_t bh0 = SMEM_LD32(B_hi, nb, kb);
                uint32_t bh1 = SMEM_LD32(B_hi, nb, kb + 8);
                uint32_t bl0 = SMEM_LD32(B_lo, nb, kb);
                uint32_t bl1 = SMEM_LD32(B_lo, nb, kb + 8);
                mma_bf16(cc[nt], ah0, ah1, ah2, ah3, bh0, bh1);
                mma_bf16(cc[nt], ah0, ah1, ah2, ah3, bl0, bl1);
                mma_bf16(cc[nt], al0, al1, al2, al3, bh0, bh1);
            }
        }
        __syncthreads();

        if (ch + 1 < nch) {
            split4_row(rA0, &A_hi[a_r][a_c], &A_lo[a_r][a_c]);
            split4_row(rA1, &A_hi[a_r + 32][a_c], &A_lo[a_r + 32][a_c]);
            #pragma unroll
            for (int j = 0; j < 4; j++) {
                split_bf16((&rB0.x)[j], B_hi[b_n + j][b_k],      B_lo[b_n + j][b_k]);
                split_bf16((&rB1.x)[j], B_hi[b_n + j][b_k + 16], B_lo[b_n + j][b_k + 16]);
            }
            __syncthreads();
        }
    }

    #pragma unroll
    for (int nt = 0; nt < 4; nt++) {
        const int col = h0 + 32 * nw + 8 * nt + qp;
        #pragma unroll
        for (int half = 0; half < 2; half++) {
            int r = m0 + 16 * mw + gq + half * 8;
            float2 o;
            o.x = cc[nt][half * 2 + 0];
            o.y = cc[nt][half * 2 + 1];
            *(float2*)&out[(size_t)r * H + col] = o;
        }
    }
}

// ---------------------------------------------------------------------------
// launch
// ---------------------------------------------------------------------------
extern "C" void kernel_launch(void* const* d_in, const int* in_sizes, int n_in,
                              void* d_out, int out_size) {
    const float* x       = (const float*)d_in[0];
    const float* gate_w  = (const float*)d_in[1];
    const float* gate_b  = (const float*)d_in[2];
    const float* w_gate  = (const float*)d_in[3];
    const float* w_up    = (const float*)d_in[4];
    const float* w_down  = (const float*)d_in[5];
    const float* sw_gate = (const float*)d_in[6];
    const float* sw_up   = (const float*)d_in[7];
    const float* sw_down = (const float*)d_in[8];
    float* out = (float*)d_out;

    init_kernel<<<1, 64>>>();
    router_kernel<<<T, 256>>>(x, gate_w, gate_b);
    shared_up_kernel<<<dim3(I / 64, T / 64), 256>>>(x, sw_gate, sw_up);
    shared_down_kernel<<<dim3(H / 64, T / 64), 256>>>(sw_down, out);
    expert_up_kernel<<<dim3(I / 64, E), 256>>>(x, w_gate, w_up);
    expert_down_kernel<<<dim3(H / 64, E), 256>>>(w_down, out);
}